// round 16
// baseline (speedup 1.0000x reference)
#include <cuda_runtime.h>
#include <cuda_fp16.h>
#include <cstdint>
#include <cstddef>

// Problem constants
#define B_  64
#define T_  320
#define E_  1024
#define H_  16
#define HS_ 64
#define M_  (B_*T_)      // 20480 tokens
#define FF_ (4*E_)       // 4096

// ===================== baseline-PTX helpers (no 'a'-arch features) =============
__device__ __forceinline__ uint32_t smem_to_u32(const void* p) {
    uint32_t a;
    asm("{ .reg .u64 t; cvta.to.shared.u64 t, %1; cvt.u32.u64 %0, t; }" : "=r"(a) : "l"(p));
    return a;
}
__device__ __forceinline__ void cp16(uint32_t s, const void* g) {
    asm volatile("cp.async.cg.shared.global [%0], [%1], 16;" :: "r"(s), "l"(g));
}
#define CP_COMMIT() asm volatile("cp.async.commit_group;" ::: "memory")
#define CP_WAIT0()  asm volatile("cp.async.wait_group 0;"  ::: "memory")
#define CP_WAIT1()  asm volatile("cp.async.wait_group 1;"  ::: "memory")
#define CP_WAIT2()  asm volatile("cp.async.wait_group 2;"  ::: "memory")

__device__ __forceinline__ void ldsm4(uint32_t* r, uint32_t addr) {
    asm volatile("ldmatrix.sync.aligned.m8n8.x4.shared.b16 {%0,%1,%2,%3}, [%4];"
        : "=r"(r[0]), "=r"(r[1]), "=r"(r[2]), "=r"(r[3]) : "r"(addr));
}
__device__ __forceinline__ void ldsm4t(uint32_t* r, uint32_t addr) {
    asm volatile("ldmatrix.sync.aligned.m8n8.x4.trans.shared.b16 {%0,%1,%2,%3}, [%4];"
        : "=r"(r[0]), "=r"(r[1]), "=r"(r[2]), "=r"(r[3]) : "r"(addr));
}
// fp16 MMA, fp32 accumulate
__device__ __forceinline__ void mma16816(float* c, const uint32_t* a,
                                         uint32_t b0, uint32_t b1) {
    asm volatile(
        "mma.sync.aligned.m16n8k16.row.col.f32.f16.f16.f32 "
        "{%0,%1,%2,%3},{%4,%5,%6,%7},{%8,%9},{%0,%1,%2,%3};"
        : "+f"(c[0]), "+f"(c[1]), "+f"(c[2]), "+f"(c[3])
        : "r"(a[0]), "r"(a[1]), "r"(a[2]), "r"(a[3]), "r"(b0), "r"(b1));
}
__device__ __forceinline__ uint32_t f22u(float a, float b) {
    __half2 h = __float22half2_rn(make_float2(a, b));
    return *(uint32_t*)&h;
}

// 128B-row XOR swizzle: conflict-free for cp.async fill and ldmatrix reads
#define SWZ128(row, cb) ((uint32_t)(((row) << 7) + ((((cb) ^ ((row) & 7))) << 4)))

// ===================== device scratch (no allocations allowed) ==================
__device__ __half g_h   [(size_t)M_*E_];     // LN output fp16
__device__ __half g_at  [(size_t)M_*E_];     // attention out [B,T,H,HS]
__device__ __half g_f1  [(size_t)M_*FF_];    // relu(h2@W1+b1)
__device__ __half g_q   [(size_t)M_*E_];     // [B,H,T,HS] fp16
__device__ __half g_k   [(size_t)M_*E_];
__device__ __half g_v   [(size_t)M_*E_];
__device__ __half g_wqkv[(size_t)3*E_*E_];   // [N=3E, K=E] fp16
__device__ __half g_wo  [(size_t)E_*E_];     // [N=E, K=E]
__device__ __half g_w1  [(size_t)FF_*E_];    // [N=4E, K=E]
__device__ __half g_w2  [(size_t)E_*FF_];    // [N=E, K=4E]

// ============ weight prep: transpose fp32 [K,N] -> fp16 [N,K] ===================
__global__ void trans_kernel(const float* __restrict__ in, int K, int N,
                             __half* __restrict__ o)
{
    __shared__ float t[32][33];
    int nb = blockIdx.x * 32, kb = blockIdx.y * 32;
    int tx = threadIdx.x, ty = threadIdx.y;          // 32 x 8
    #pragma unroll
    for (int j = 0; j < 4; j++)
        t[ty + j*8][tx] = in[(size_t)(kb + ty + j*8) * N + nb + tx];
    __syncthreads();
    #pragma unroll
    for (int j = 0; j < 4; j++) {
        float v = t[tx][ty + j*8];
        int orow = nb + ty + j*8, ocol = kb + tx;
        o[(size_t)orow * K + ocol] = __float2half_rn(v);
    }
}

// Wq/Wk/Wv (H,E,HS) -> [3E rows, E cols] transposed fp16
__global__ void trans_qkv_kernel(const float* __restrict__ Wq,
                                 const float* __restrict__ Wk,
                                 const float* __restrict__ Wv,
                                 __half* __restrict__ o)
{
    __shared__ float t[32][33];
    int z = blockIdx.z;
    const float* W = (z < 16) ? Wq : (z < 32) ? Wk : Wv;
    const float* in = W + (size_t)(z & 15) * E_ * HS_;
    int nb = blockIdx.x * 32, kb = blockIdx.y * 32;
    int tx = threadIdx.x, ty = threadIdx.y;
    #pragma unroll
    for (int j = 0; j < 4; j++)
        t[ty + j*8][tx] = in[(size_t)(kb + ty + j*8) * HS_ + nb + tx];
    __syncthreads();
    #pragma unroll
    for (int j = 0; j < 4; j++) {
        float v = t[tx][ty + j*8];
        int orow = z * 64 + nb + ty + j*8;
        int ocol = kb + tx;
        o[(size_t)orow * E_ + ocol] = __float2half_rn(v);
    }
}

// ================= layernorm -> fp16 ============================================
__global__ void __launch_bounds__(256) ln_kernel(const float* __restrict__ x,
                                                 const float* __restrict__ w,
                                                 const float* __restrict__ b,
                                                 __half* __restrict__ o)
{
    int row = blockIdx.x;
    int t = threadIdx.x;
    float4 v = ((const float4*)(x + (size_t)row * E_))[t];
    float s  = v.x + v.y + v.z + v.w;
    float sq = v.x*v.x + v.y*v.y + v.z*v.z + v.w*v.w;
    #pragma unroll
    for (int off = 16; off; off >>= 1) {
        s  += __shfl_xor_sync(0xffffffffu, s,  off);
        sq += __shfl_xor_sync(0xffffffffu, sq, off);
    }
    __shared__ float ss[8], ssq[8];
    int warp = t >> 5, lane = t & 31;
    if (lane == 0) { ss[warp] = s; ssq[warp] = sq; }
    __syncthreads();
    float tot = 0.f, totq = 0.f;
    #pragma unroll
    for (int i = 0; i < 8; i++) { tot += ss[i]; totq += ssq[i]; }
    float mu  = tot * (1.0f / E_);
    float var = totq * (1.0f / E_) - mu * mu;
    float rs  = rsqrtf(var + 1e-5f);
    float4 w4 = ((const float4*)w)[t];
    float4 b4 = ((const float4*)b)[t];
    float r0 = (v.x - mu) * rs * w4.x + b4.x;
    float r1 = (v.y - mu) * rs * w4.y + b4.y;
    float r2 = (v.z - mu) * rs * w4.z + b4.z;
    float r3 = (v.w - mu) * rs * w4.w + b4.w;
    uint2 p = { f22u(r0, r1), f22u(r2, r3) };
    ((uint2*)(o + (size_t)row * E_))[t] = p;
}

// ================= mma.sync fp16 GEMM ===========================================
// C[M,N] = A[M,K] * B[N,K]^T. 128x256 block tile, 16 warps (4x4),
// warp tile 32x64, K-chunk 64, 4-stage cp.async pipeline (prefetch distance 3).
// EPI 0: scatter fp16 q/k/v   EPI 1: fp32 out = acc+bias+resid
// EPI 2: fp16 out = relu(acc+bias)
#define ST_A     16384                 // A: 128 rows x 128B
#define ST_B     32768                 // B: 256 rows x 128B
#define STAGE_SZ (ST_A+ST_B)           // 48 KB
#define NSTAGE   4
#define SMEM_GEMM (NSTAGE*STAGE_SZ)    // 192 KB

template<int EPI>
__global__ void __launch_bounds__(512, 1) tgemm_kernel(
    const __half* __restrict__ A, const __half* __restrict__ Bw,
    int M, int N, int K,
    const float* __restrict__ bias, const float* __restrict__ resid,
    float* __restrict__ outf, __half* __restrict__ outh,
    __half* __restrict__ qo, __half* __restrict__ ko, __half* __restrict__ vo)
{
    extern __shared__ char smem[];
    uint32_t sb = smem_to_u32(smem);
    int tid  = threadIdx.x;
    int lane = tid & 31, wid = tid >> 5;
    int bm = blockIdx.y, bn = blockIdx.x;
    int wm = wid >> 2, wn = wid & 3;        // 4x4 warp grid

    const char* pA = (const char*)A;
    const char* pB = (const char*)Bw;
    const int K2 = K * 2;                    // bytes per row
    const size_t aBase = (size_t)(bm * 128) * K2;
    const size_t bBase = (size_t)(bn * 256) * K2;
    const int nch = K >> 6;                  // 64-K chunks

    int a_row = wm * 32 + (lane & 15);       // warp tile rows: wm*32..+31
    int a_cbo = lane >> 4;                   // 0/1
    int bg = lane >> 3, br = lane & 7;
    int b_row = wn * 64 + ((bg >> 1) << 3) + br;
    int b_cbo = bg & 1;

    float acc[2][8][4];
    #pragma unroll
    for (int a = 0; a < 2; a++)
        #pragma unroll
        for (int nb = 0; nb < 8; nb++)
            #pragma unroll
            for (int i = 0; i < 4; i++) acc[a][nb][i] = 0.f;

    // stage loader (512 thr): A 2 chunks/thread, B 4 chunks/thread (16B each)
    #define LOAD_STAGE(sidx, kbyte) do {                                        \
        uint32_t s_ = sb + (uint32_t)(sidx) * STAGE_SZ;                          \
        _Pragma("unroll")                                                        \
        for (int j = 0; j < 2; j++) {                                            \
            int idx = tid + j * 512;                                             \
            int row = idx >> 3, cb = idx & 7;                                    \
            cp16(s_ + SWZ128(row, cb),                                           \
                 pA + aBase + (size_t)row * K2 + (kbyte) + cb * 16);             \
        }                                                                        \
        _Pragma("unroll")                                                        \
        for (int j = 0; j < 4; j++) {                                            \
            int idx = tid + j * 512;                                             \
            int row = idx >> 3, cb = idx & 7;                                    \
            cp16(s_ + ST_A + SWZ128(row, cb),                                    \
                 pB + bBase + (size_t)row * K2 + (kbyte) + cb * 16);             \
        }                                                                        \
    } while (0)

    // prologue: chunks 0..2 in flight
    LOAD_STAGE(0, 0);
    CP_COMMIT();
    LOAD_STAGE(1, 128);
    CP_COMMIT();
    LOAD_STAGE(2, 256);
    CP_COMMIT();

    int sidx = 0;                            // stage of chunk c
    for (int c = 0; c < nch; c++) {
        CP_WAIT2();                          // chunk c's group complete
        __syncthreads();
        // prefetch chunk c+3 (always commit to keep group counts uniform)
        if (c + 3 < nch) {
            int nsi = sidx + 3; if (nsi >= NSTAGE) nsi -= NSTAGE;
            LOAD_STAGE(nsi, (size_t)(c + 3) * 128);
        }
        CP_COMMIT();

        uint32_t s = sb + (uint32_t)sidx * STAGE_SZ;
        #pragma unroll
        for (int ks = 0; ks < 4; ks++) {
            uint32_t af[2][4];
            int acb = ks * 2 + a_cbo;
            #pragma unroll
            for (int a = 0; a < 2; a++)
                ldsm4(af[a], s + SWZ128(a_row + a * 16, acb));
            uint32_t bf[4][4];
            int bcb = ks * 2 + b_cbo;
            #pragma unroll
            for (int p = 0; p < 4; p++)
                ldsm4(bf[p], s + ST_A + SWZ128(b_row + p * 16, bcb));
            #pragma unroll
            for (int p = 0; p < 4; p++)
                #pragma unroll
                for (int h = 0; h < 2; h++) {
                    int nb = p * 2 + h;
                    #pragma unroll
                    for (int a = 0; a < 2; a++)
                        mma16816(acc[a][nb], af[a], bf[p][2*h], bf[p][2*h+1]);
                }
        }
        sidx++; if (sidx >= NSTAGE) sidx = 0;
    }
    #undef LOAD_STAGE

    // ---- epilogue ----
    int erow0 = bm * 128 + wm * 32 + (lane >> 2);
    int ecol0 = bn * 256 + wn * 64 + 2 * (lane & 3);

    #pragma unroll
    for (int a = 0; a < 2; a++) {
        #pragma unroll
        for (int nb = 0; nb < 8; nb++) {
            int gn = ecol0 + nb * 8;
            #pragma unroll
            for (int half = 0; half < 2; half++) {
                int gm = erow0 + a * 16 + half * 8;
                float v0 = acc[a][nb][half * 2 + 0];
                float v1 = acc[a][nb][half * 2 + 1];
                if (EPI == 0) {
                    int which = gn >> 10;
                    int w = gn & (E_ - 1);
                    int hh = w >> 6, dd = w & 63;
                    int bk = gm / T_, tt = gm - bk * T_;
                    __half* dst = (which == 0) ? qo : (which == 1) ? ko : vo;
                    uint32_t o = f22u(v0, v1);
                    *(uint32_t*)(dst + (((size_t)(bk * H_ + hh)) * T_ + tt) * HS_ + dd) = o;
                } else if (EPI == 1) {
                    const float2 bv = *(const float2*)(bias + gn);
                    const float2 rv = *(const float2*)(resid + (size_t)gm * N + gn);
                    float2 o = {v0 + bv.x + rv.x, v1 + bv.y + rv.y};
                    *(float2*)(outf + (size_t)gm * N + gn) = o;
                } else {
                    const float2 bv = *(const float2*)(bias + gn);
                    uint32_t o = f22u(fmaxf(v0 + bv.x, 0.f), fmaxf(v1 + bv.y, 0.f));
                    *(uint32_t*)(outh + (size_t)gm * N + gn) = o;
                }
            }
        }
    }
}

// ================= HMMA flash attention =========================================
// fp16 QKV [B,H,T,HS], HS=64. Block: 128 thr (4 warps), 64-query tile.
#define KVOFF(row, cb) SWZ128(row, cb)

__global__ void __launch_bounds__(128) attn_kernel(
    const __half* __restrict__ Qg, const __half* __restrict__ Kg,
    const __half* __restrict__ Vg, __half* __restrict__ Og)
{
    __shared__ __half Qs[4096];
    __shared__ __half Ks[2][4096];
    __shared__ __half Vs[2][4096];

    int qt = blockIdx.x, bh = blockIdx.y;
    int q0 = qt * 64;
    int tid = threadIdx.x, lane = tid & 31, w = tid >> 5;
    const char* qg = (const char*)(Qg + (size_t)bh * T_ * HS_) + (size_t)q0 * 128;
    const char* kg = (const char*)(Kg + (size_t)bh * T_ * HS_);
    const char* vg = (const char*)(Vg + (size_t)bh * T_ * HS_);
    uint32_t sq = smem_to_u32(Qs);
    uint32_t sk0 = smem_to_u32(Ks[0]), sk1 = smem_to_u32(Ks[1]);
    uint32_t sv0 = smem_to_u32(Vs[0]), sv1 = smem_to_u32(Vs[1]);

    #pragma unroll
    for (int j = 0; j < 4; j++) {
        int i = tid + j * 128;
        int row = i >> 3, cb = i & 7;
        uint32_t o = KVOFF(row, cb);
        size_t g = (size_t)row * 128 + cb * 16;
        cp16(sq + o, qg + g);
        cp16(sk0 + o, kg + g);
        cp16(sv0 + o, vg + g);
    }
    CP_COMMIT();
    CP_WAIT0();
    __syncthreads();

    int mid = lane >> 3, r8 = lane & 7;
    uint32_t afr[4][4];
    #pragma unroll
    for (int s = 0; s < 4; s++) {
        int row = 16 * w + ((mid & 1) << 3) + r8;
        int cb = s * 2 + (mid >> 1);
        ldsm4(afr[s], sq + KVOFF(row, cb));
    }

    float o_acc[8][4];
    #pragma unroll
    for (int a = 0; a < 8; a++)
        #pragma unroll
        for (int i = 0; i < 4; i++) o_acc[a][i] = 0.f;
    float mr0 = -1e30f, mr1 = -1e30f, lr0 = 0.f, lr1 = 0.f;

    int nkt = qt + 1;
    int myrow0 = 16 * w + (lane >> 2);
    int mycol0 = 2 * (lane & 3);

    for (int kt = 0; kt < nkt; kt++) {
        __syncthreads();
        if (kt + 1 < nkt) {
            uint32_t dk = (kt & 1) ? sk0 : sk1;
            uint32_t dv = (kt & 1) ? sv0 : sv1;
            const char* kg_ = kg + (size_t)(kt + 1) * 64 * 128;
            const char* vg_ = vg + (size_t)(kt + 1) * 64 * 128;
            #pragma unroll
            for (int j = 0; j < 4; j++) {
                int i = tid + j * 128;
                int row = i >> 3, cb = i & 7;
                uint32_t o = KVOFF(row, cb);
                size_t g = (size_t)row * 128 + cb * 16;
                cp16(dk + o, kg_ + g);
                cp16(dv + o, vg_ + g);
            }
        }
        CP_COMMIT();
        CP_WAIT1();
        __syncthreads();

        uint32_t skb = (kt & 1) ? sk1 : sk0;
        uint32_t svb = (kt & 1) ? sv1 : sv0;

        float sA[8][4];
        #pragma unroll
        for (int e = 0; e < 8; e++)
            #pragma unroll
            for (int i = 0; i < 4; i++) sA[e][i] = 0.f;
        #pragma unroll
        for (int s = 0; s < 4; s++) {
            #pragma unroll
            for (int j = 0; j < 4; j++) {
                int row = j * 16 + ((mid >> 1) << 3) + r8;
                int cb = s * 2 + (mid & 1);
                uint32_t bk[4];
                ldsm4(bk, skb + KVOFF(row, cb));
                mma16816(sA[2*j],   afr[s], bk[0], bk[1]);
                mma16816(sA[2*j+1], afr[s], bk[2], bk[3]);
            }
        }

        #pragma unroll
        for (int e = 0; e < 8; e++)
            #pragma unroll
            for (int i = 0; i < 4; i++) sA[e][i] *= 0.03125f;
        if (kt == qt) {
            #pragma unroll
            for (int e = 0; e < 8; e++) {
                int kc = e * 8 + mycol0;
                if (kc     > myrow0)     sA[e][0] = -1e30f;
                if (kc + 1 > myrow0)     sA[e][1] = -1e30f;
                if (kc     > myrow0 + 8) sA[e][2] = -1e30f;
                if (kc + 1 > myrow0 + 8) sA[e][3] = -1e30f;
            }
        }

        float mx0 = -1e30f, mx1 = -1e30f;
        #pragma unroll
        for (int e = 0; e < 8; e++) {
            mx0 = fmaxf(mx0, fmaxf(sA[e][0], sA[e][1]));
            mx1 = fmaxf(mx1, fmaxf(sA[e][2], sA[e][3]));
        }
        mx0 = fmaxf(mx0, __shfl_xor_sync(0xffffffffu, mx0, 1));
        mx0 = fmaxf(mx0, __shfl_xor_sync(0xffffffffu, mx0, 2));
        mx1 = fmaxf(mx1, __shfl_xor_sync(0xffffffffu, mx1, 1));
        mx1 = fmaxf(mx1, __shfl_xor_sync(0xffffffffu, mx1, 2));
        float mn0 = fmaxf(mr0, mx0), mn1 = fmaxf(mr1, mx1);
        float al0 = __expf(mr0 - mn0), al1 = __expf(mr1 - mn1);
        mr0 = mn0; mr1 = mn1;

        float sum0 = 0.f, sum1 = 0.f;
        uint32_t pa[4][4];
        #pragma unroll
        for (int e = 0; e < 8; e++) {
            float p0 = __expf(sA[e][0] - mn0);
            float p1 = __expf(sA[e][1] - mn0);
            float p2 = __expf(sA[e][2] - mn1);
            float p3 = __expf(sA[e][3] - mn1);
            sum0 += p0 + p1; sum1 += p2 + p3;
            int t = e >> 1, od = (e & 1) * 2;
            pa[t][od]     = f22u(p0, p1);
            pa[t][od + 1] = f22u(p2, p3);
        }
        sum0 += __shfl_xor_sync(0xffffffffu, sum0, 1);
        sum0 += __shfl_xor_sync(0xffffffffu, sum0, 2);
        sum1 += __shfl_xor_sync(0xffffffffu, sum1, 1);
        sum1 += __shfl_xor_sync(0xffffffffu, sum1, 2);
        lr0 = lr0 * al0 + sum0;
        lr1 = lr1 * al1 + sum1;

        #pragma unroll
        for (int a = 0; a < 8; a++) {
            o_acc[a][0] *= al0; o_acc[a][1] *= al0;
            o_acc[a][2] *= al1; o_acc[a][3] *= al1;
        }

        #pragma unroll
        for (int t = 0; t < 4; t++) {
            #pragma unroll
            for (int j = 0; j < 4; j++) {
                int row = t * 16 + ((mid & 1) << 3) + r8;
                int cb = j * 2 + (mid >> 1);
                uint32_t bv[4];
                ldsm4t(bv, svb + KVOFF(row, cb));
                mma16816(o_acc[2*j],   pa[t], bv[0], bv[1]);
                mma16816(o_acc[2*j+1], pa[t], bv[2], bv[3]);
            }
        }
    }

    float inv0 = 1.0f / lr0, inv1 = 1.0f / lr1;
    int b = bh >> 4, h = bh & 15;
    int gr0 = q0 + myrow0, gr1 = gr0 + 8;
    #pragma unroll
    for (int a = 0; a < 8; a++) {
        int d = a * 8 + mycol0;
        *(uint32_t*)(Og + (((size_t)(b * T_ + gr0)) * H_ + h) * HS_ + d) =
            f22u(o_acc[a][0] * inv0, o_acc[a][1] * inv0);
        *(uint32_t*)(Og + (((size_t)(b * T_ + gr1)) * H_ + h) * HS_ + d) =
            f22u(o_acc[a][2] * inv1, o_acc[a][3] * inv1);
    }
}

// ---------------- launch --------------------------------------------------------
extern "C" void kernel_launch(void* const* d_in, const int* in_sizes, int n_in,
                              void* d_out, int out_size)
{
    const float* x    = (const float*)d_in[0];
    const float* Wq   = (const float*)d_in[1];
    const float* Wk   = (const float*)d_in[2];
    const float* Wv   = (const float*)d_in[3];
    const float* Wo   = (const float*)d_in[4];
    const float* bo   = (const float*)d_in[5];
    const float* W1   = (const float*)d_in[6];
    const float* b1   = (const float*)d_in[7];
    const float* W2   = (const float*)d_in[8];
    const float* b2   = (const float*)d_in[9];
    const float* ln1w = (const float*)d_in[10];
    const float* ln1b = (const float*)d_in[11];
    const float* ln2w = (const float*)d_in[12];
    const float* ln2b = (const float*)d_in[13];
    float* out = (float*)d_out;

    __half *ph, *pat, *pf1, *pq, *pk, *pv, *wqkv, *wo, *w1, *w2;
    cudaGetSymbolAddress((void**)&ph,   g_h);
    cudaGetSymbolAddress((void**)&pat,  g_at);
    cudaGetSymbolAddress((void**)&pf1,  g_f1);
    cudaGetSymbolAddress((void**)&pq,   g_q);
    cudaGetSymbolAddress((void**)&pk,   g_k);
    cudaGetSymbolAddress((void**)&pv,   g_v);
    cudaGetSymbolAddress((void**)&wqkv, g_wqkv);
    cudaGetSymbolAddress((void**)&wo,   g_wo);
    cudaGetSymbolAddress((void**)&w1,   g_w1);
    cudaGetSymbolAddress((void**)&w2,   g_w2);

    cudaFuncSetAttribute(tgemm_kernel<0>, cudaFuncAttributeMaxDynamicSharedMemorySize, SMEM_GEMM);
    cudaFuncSetAttribute(tgemm_kernel<1>, cudaFuncAttributeMaxDynamicSharedMemorySize, SMEM_GEMM);
    cudaFuncSetAttribute(tgemm_kernel<2>, cudaFuncAttributeMaxDynamicSharedMemorySize, SMEM_GEMM);

    dim3 tb(32, 8);

    // weight prep (transpose to fp16 [N,K])
    trans_qkv_kernel<<<dim3(2, 32, 48), tb>>>(Wq, Wk, Wv, wqkv);
    trans_kernel<<<dim3(32, 32), tb>>>(Wo, E_, E_, wo);
    trans_kernel<<<dim3(128, 32), tb>>>(W1, E_, FF_, w1);
    trans_kernel<<<dim3(32, 128), tb>>>(W2, FF_, E_, w2);

    // h = LN1(x) -> fp16
    ln_kernel<<<M_, 256>>>(x, ln1w, ln1b, ph);

    // q,k,v = h @ Wqkv (scatter fp16 [B,H,T,HS])
    tgemm_kernel<0><<<dim3(3*E_/256, M_/128), 512, SMEM_GEMM>>>(
        ph, wqkv, M_, 3*E_, E_,
        nullptr, nullptr, nullptr, nullptr, pq, pk, pv);

    // attention (HMMA flash) -> fp16 [B,T,H,HS]
    attn_kernel<<<dim3(T_/64, B_*H_), 128>>>(pq, pk, pv, pat);

    // x1 = x + attn @ Wo + bo  (fp32, into d_out)
    tgemm_kernel<1><<<dim3(E_/256, M_/128), 512, SMEM_GEMM>>>(
        pat, wo, M_, E_, E_,
        bo, x, out, nullptr, nullptr, nullptr, nullptr);

    // h2 = LN2(x1) -> fp16
    ln_kernel<<<M_, 256>>>(out, ln2w, ln2b, ph);

    // f1 = relu(h2 @ W1 + b1) -> fp16
    tgemm_kernel<2><<<dim3(FF_/256, M_/128), 512, SMEM_GEMM>>>(
        ph, w1, M_, FF_, E_,
        b1, nullptr, nullptr, pf1, nullptr, nullptr, nullptr);

    // out = x1 + f1 @ W2 + b2
    tgemm_kernel<1><<<dim3(E_/256, M_/128), 512, SMEM_GEMM>>>(
        pf1, w2, M_, E_, FF_,
        b2, out, out, nullptr, nullptr, nullptr, nullptr);
}

// round 17
// speedup vs baseline: 1.0520x; 1.0520x over previous
#include <cuda_runtime.h>
#include <cuda_fp16.h>
#include <cstdint>
#include <cstddef>

// Problem constants
#define B_  64
#define T_  320
#define E_  1024
#define H_  16
#define HS_ 64
#define M_  (B_*T_)      // 20480 tokens
#define FF_ (4*E_)       // 4096

// ===================== baseline-PTX helpers (no 'a'-arch features) =============
__device__ __forceinline__ uint32_t smem_to_u32(const void* p) {
    uint32_t a;
    asm("{ .reg .u64 t; cvta.to.shared.u64 t, %1; cvt.u32.u64 %0, t; }" : "=r"(a) : "l"(p));
    return a;
}
__device__ __forceinline__ void cp16(uint32_t s, const void* g) {
    asm volatile("cp.async.cg.shared.global [%0], [%1], 16;" :: "r"(s), "l"(g));
}
#define CP_COMMIT() asm volatile("cp.async.commit_group;" ::: "memory")
#define CP_WAIT0()  asm volatile("cp.async.wait_group 0;"  ::: "memory")
#define CP_WAIT1()  asm volatile("cp.async.wait_group 1;"  ::: "memory")

__device__ __forceinline__ void ldsm4(uint32_t* r, uint32_t addr) {
    asm volatile("ldmatrix.sync.aligned.m8n8.x4.shared.b16 {%0,%1,%2,%3}, [%4];"
        : "=r"(r[0]), "=r"(r[1]), "=r"(r[2]), "=r"(r[3]) : "r"(addr));
}
__device__ __forceinline__ void ldsm4t(uint32_t* r, uint32_t addr) {
    asm volatile("ldmatrix.sync.aligned.m8n8.x4.trans.shared.b16 {%0,%1,%2,%3}, [%4];"
        : "=r"(r[0]), "=r"(r[1]), "=r"(r[2]), "=r"(r[3]) : "r"(addr));
}
// fp16 MMA, fp32 accumulate
__device__ __forceinline__ void mma16816(float* c, const uint32_t* a,
                                         uint32_t b0, uint32_t b1) {
    asm volatile(
        "mma.sync.aligned.m16n8k16.row.col.f32.f16.f16.f32 "
        "{%0,%1,%2,%3},{%4,%5,%6,%7},{%8,%9},{%0,%1,%2,%3};"
        : "+f"(c[0]), "+f"(c[1]), "+f"(c[2]), "+f"(c[3])
        : "r"(a[0]), "r"(a[1]), "r"(a[2]), "r"(a[3]), "r"(b0), "r"(b1));
}
__device__ __forceinline__ uint32_t f22u(float a, float b) {
    __half2 h = __float22half2_rn(make_float2(a, b));
    return *(uint32_t*)&h;
}

// 128B-row XOR swizzle (attention tiles)
#define SWZ128(row, cb) ((uint32_t)(((row) << 7) + ((((cb) ^ ((row) & 7))) << 4)))
// 256B-row XOR swizzle (GEMM tiles): permute chunk low-3-bits by row&7
#define SWZ256(row, cb) ((uint32_t)(((row) << 8) + (((((cb) & 8) | (((cb) ^ ((row) & 7)) & 7))) << 4)))

// ===================== device scratch (no allocations allowed) ==================
__device__ __half g_h   [(size_t)M_*E_];     // LN output fp16
__device__ __half g_at  [(size_t)M_*E_];     // attention out [B,T,H,HS]
__device__ __half g_f1  [(size_t)M_*FF_];    // relu(h2@W1+b1)
__device__ __half g_q   [(size_t)M_*E_];     // [B,H,T,HS] fp16
__device__ __half g_k   [(size_t)M_*E_];
__device__ __half g_v   [(size_t)M_*E_];
__device__ __half g_wqkv[(size_t)3*E_*E_];   // [N=3E, K=E] fp16
__device__ __half g_wo  [(size_t)E_*E_];     // [N=E, K=E]
__device__ __half g_w1  [(size_t)FF_*E_];    // [N=4E, K=E]
__device__ __half g_w2  [(size_t)E_*FF_];    // [N=E, K=4E]

// ============ weight prep: transpose fp32 [K,N] -> fp16 [N,K] ===================
__global__ void trans_kernel(const float* __restrict__ in, int K, int N,
                             __half* __restrict__ o)
{
    __shared__ float t[32][33];
    int nb = blockIdx.x * 32, kb = blockIdx.y * 32;
    int tx = threadIdx.x, ty = threadIdx.y;          // 32 x 8
    #pragma unroll
    for (int j = 0; j < 4; j++)
        t[ty + j*8][tx] = in[(size_t)(kb + ty + j*8) * N + nb + tx];
    __syncthreads();
    #pragma unroll
    for (int j = 0; j < 4; j++) {
        float v = t[tx][ty + j*8];
        int orow = nb + ty + j*8, ocol = kb + tx;
        o[(size_t)orow * K + ocol] = __float2half_rn(v);
    }
}

// Wq/Wk/Wv (H,E,HS) -> [3E rows, E cols] transposed fp16
__global__ void trans_qkv_kernel(const float* __restrict__ Wq,
                                 const float* __restrict__ Wk,
                                 const float* __restrict__ Wv,
                                 __half* __restrict__ o)
{
    __shared__ float t[32][33];
    int z = blockIdx.z;
    const float* W = (z < 16) ? Wq : (z < 32) ? Wk : Wv;
    const float* in = W + (size_t)(z & 15) * E_ * HS_;
    int nb = blockIdx.x * 32, kb = blockIdx.y * 32;
    int tx = threadIdx.x, ty = threadIdx.y;
    #pragma unroll
    for (int j = 0; j < 4; j++)
        t[ty + j*8][tx] = in[(size_t)(kb + ty + j*8) * HS_ + nb + tx];
    __syncthreads();
    #pragma unroll
    for (int j = 0; j < 4; j++) {
        float v = t[tx][ty + j*8];
        int orow = z * 64 + nb + ty + j*8;
        int ocol = kb + tx;
        o[(size_t)orow * E_ + ocol] = __float2half_rn(v);
    }
}

// ================= layernorm -> fp16, warp-per-row ==============================
// 256 thr = 8 warps = 8 rows/block; 32 threads per row, 8 float4 each, shfl-only.
__global__ void __launch_bounds__(256) ln_kernel(const float* __restrict__ x,
                                                 const float* __restrict__ w,
                                                 const float* __restrict__ b,
                                                 __half* __restrict__ o)
{
    int row = blockIdx.x * 8 + (threadIdx.x >> 5);
    int t = threadIdx.x & 31;
    const float4* xr = (const float4*)(x + (size_t)row * E_);
    float4 v[8];
    float s = 0.f, sq = 0.f;
    #pragma unroll
    for (int i = 0; i < 8; i++) {
        v[i] = xr[t + 32 * i];
        s  += v[i].x + v[i].y + v[i].z + v[i].w;
        sq += v[i].x*v[i].x + v[i].y*v[i].y + v[i].z*v[i].z + v[i].w*v[i].w;
    }
    #pragma unroll
    for (int off = 16; off; off >>= 1) {
        s  += __shfl_xor_sync(0xffffffffu, s,  off);
        sq += __shfl_xor_sync(0xffffffffu, sq, off);
    }
    float mu  = s * (1.0f / E_);
    float var = sq * (1.0f / E_) - mu * mu;
    float rs  = rsqrtf(var + 1e-5f);
    uint2* orow = (uint2*)(o + (size_t)row * E_);
    const float4* wp = (const float4*)w;
    const float4* bp = (const float4*)b;
    #pragma unroll
    for (int i = 0; i < 8; i++) {
        float4 w4 = wp[t + 32 * i];
        float4 b4 = bp[t + 32 * i];
        float r0 = (v[i].x - mu) * rs * w4.x + b4.x;
        float r1 = (v[i].y - mu) * rs * w4.y + b4.y;
        float r2 = (v[i].z - mu) * rs * w4.z + b4.z;
        float r3 = (v[i].w - mu) * rs * w4.w + b4.w;
        uint2 p = { f22u(r0, r1), f22u(r2, r3) };
        orow[t + 32 * i] = p;
    }
}

// ================= mma.sync fp16 GEMM ===========================================
// C[M,N] = A[M,K] * B[N,K]^T. 128x256 block tile, 8 warps (2x4), warp tile 64x64,
// K-chunk 128, 2-stage cp.async pipeline (one barrier per chunk, 8/GEMM).
// EPI 0: scatter fp16 q/k/v   EPI 1: fp32 out = acc+bias+resid
// EPI 2: fp16 out = relu(acc+bias)
#define ST_A     32768                 // A: 128 rows x 256B
#define ST_B     65536                 // B: 256 rows x 256B
#define STAGE_SZ (ST_A+ST_B)           // 96 KB
#define SMEM_GEMM (2*STAGE_SZ)         // 192 KB

template<int EPI>
__global__ void __launch_bounds__(256, 1) tgemm_kernel(
    const __half* __restrict__ A, const __half* __restrict__ Bw,
    int M, int N, int K,
    const float* __restrict__ bias, const float* __restrict__ resid,
    float* __restrict__ outf, __half* __restrict__ outh,
    __half* __restrict__ qo, __half* __restrict__ ko, __half* __restrict__ vo)
{
    extern __shared__ char smem[];
    uint32_t sb = smem_to_u32(smem);
    int tid  = threadIdx.x;
    int lane = tid & 31, wid = tid >> 5;
    int bm = blockIdx.y, bn = blockIdx.x;
    int wm = wid >> 2, wn = wid & 3;

    const char* pA = (const char*)A;
    const char* pB = (const char*)Bw;
    const int K2 = K * 2;                    // bytes per row
    const size_t aBase = (size_t)(bm * 128) * K2;
    const size_t bBase = (size_t)(bn * 256) * K2;
    const int nch = K >> 7;                  // 128-K chunks

    int a_row = wm * 64 + (lane & 15);
    int a_cbo = lane >> 4;                   // 0/1
    int bg = lane >> 3, br = lane & 7;
    int b_row = wn * 64 + ((bg >> 1) << 3) + br;
    int b_cbo = bg & 1;

    float acc[4][8][4];
    #pragma unroll
    for (int a = 0; a < 4; a++)
        #pragma unroll
        for (int nb = 0; nb < 8; nb++)
            #pragma unroll
            for (int i = 0; i < 4; i++) acc[a][nb][i] = 0.f;

    // stage loader: A 8 chunks/thread, B 16 chunks/thread (16B each)
    #define LOAD_STAGE(sidx, kbyte) do {                                        \
        uint32_t s_ = sb + (uint32_t)(sidx) * STAGE_SZ;                          \
        _Pragma("unroll")                                                        \
        for (int j = 0; j < 8; j++) {                                            \
            int idx = tid + j * 256;                                             \
            int row = idx >> 4, cb = idx & 15;                                   \
            cp16(s_ + SWZ256(row, cb),                                           \
                 pA + aBase + (size_t)row * K2 + (kbyte) + cb * 16);             \
        }                                                                        \
        _Pragma("unroll")                                                        \
        for (int j = 0; j < 16; j++) {                                           \
            int idx = tid + j * 256;                                             \
            int row = idx >> 4, cb = idx & 15;                                   \
            cp16(s_ + ST_A + SWZ256(row, cb),                                    \
                 pB + bBase + (size_t)row * K2 + (kbyte) + cb * 16);             \
        }                                                                        \
    } while (0)

    LOAD_STAGE(0, 0);
    CP_COMMIT();

    for (int c = 0; c < nch; c++) {
        CP_WAIT0();
        __syncthreads();
        if (c + 1 < nch) {
            LOAD_STAGE((c + 1) & 1, (size_t)(c + 1) * 256);
            CP_COMMIT();
        }
        uint32_t s = sb + (uint32_t)(c & 1) * STAGE_SZ;
        #pragma unroll
        for (int ks = 0; ks < 8; ks++) {
            uint32_t af[4][4];
            int acb = ks * 2 + a_cbo;
            #pragma unroll
            for (int a = 0; a < 4; a++)
                ldsm4(af[a], s + SWZ256(a_row + a * 16, acb));
            uint32_t bf[4][4];
            int bcb = ks * 2 + b_cbo;
            #pragma unroll
            for (int p = 0; p < 4; p++)
                ldsm4(bf[p], s + ST_A + SWZ256(b_row + p * 16, bcb));
            #pragma unroll
            for (int p = 0; p < 4; p++)
                #pragma unroll
                for (int h = 0; h < 2; h++) {
                    int nb = p * 2 + h;
                    #pragma unroll
                    for (int a = 0; a < 4; a++)
                        mma16816(acc[a][nb], af[a], bf[p][2*h], bf[p][2*h+1]);
                }
        }
    }
    #undef LOAD_STAGE

    // ---- epilogue ----
    int erow0 = bm * 128 + wm * 64 + (lane >> 2);
    int ecol0 = bn * 256 + wn * 64 + 2 * (lane & 3);

    #pragma unroll
    for (int a = 0; a < 4; a++) {
        #pragma unroll
        for (int nb = 0; nb < 8; nb++) {
            int gn = ecol0 + nb * 8;
            #pragma unroll
            for (int half = 0; half < 2; half++) {
                int gm = erow0 + a * 16 + half * 8;
                float v0 = acc[a][nb][half * 2 + 0];
                float v1 = acc[a][nb][half * 2 + 1];
                if (EPI == 0) {
                    int which = gn >> 10;
                    int w = gn & (E_ - 1);
                    int hh = w >> 6, dd = w & 63;
                    int bk = gm / T_, tt = gm - bk * T_;
                    __half* dst = (which == 0) ? qo : (which == 1) ? ko : vo;
                    uint32_t o = f22u(v0, v1);
                    *(uint32_t*)(dst + (((size_t)(bk * H_ + hh)) * T_ + tt) * HS_ + dd) = o;
                } else if (EPI == 1) {
                    const float2 bv = *(const float2*)(bias + gn);
                    const float2 rv = *(const float2*)(resid + (size_t)gm * N + gn);
                    float2 o = {v0 + bv.x + rv.x, v1 + bv.y + rv.y};
                    *(float2*)(outf + (size_t)gm * N + gn) = o;
                } else {
                    const float2 bv = *(const float2*)(bias + gn);
                    uint32_t o = f22u(fmaxf(v0 + bv.x, 0.f), fmaxf(v1 + bv.y, 0.f));
                    *(uint32_t*)(outh + (size_t)gm * N + gn) = o;
                }
            }
        }
    }
}

// ================= HMMA flash attention =========================================
// fp16 QKV [B,H,T,HS], HS=64. Block: 128 thr (4 warps), 64-query tile.
#define KVOFF(row, cb) SWZ128(row, cb)

__global__ void __launch_bounds__(128) attn_kernel(
    const __half* __restrict__ Qg, const __half* __restrict__ Kg,
    const __half* __restrict__ Vg, __half* __restrict__ Og)
{
    __shared__ __half Qs[4096];
    __shared__ __half Ks[2][4096];
    __shared__ __half Vs[2][4096];

    int qt = blockIdx.x, bh = blockIdx.y;
    int q0 = qt * 64;
    int tid = threadIdx.x, lane = tid & 31, w = tid >> 5;
    const char* qg = (const char*)(Qg + (size_t)bh * T_ * HS_) + (size_t)q0 * 128;
    const char* kg = (const char*)(Kg + (size_t)bh * T_ * HS_);
    const char* vg = (const char*)(Vg + (size_t)bh * T_ * HS_);
    uint32_t sq = smem_to_u32(Qs);
    uint32_t sk0 = smem_to_u32(Ks[0]), sk1 = smem_to_u32(Ks[1]);
    uint32_t sv0 = smem_to_u32(Vs[0]), sv1 = smem_to_u32(Vs[1]);

    #pragma unroll
    for (int j = 0; j < 4; j++) {
        int i = tid + j * 128;
        int row = i >> 3, cb = i & 7;
        uint32_t o = KVOFF(row, cb);
        size_t g = (size_t)row * 128 + cb * 16;
        cp16(sq + o, qg + g);
        cp16(sk0 + o, kg + g);
        cp16(sv0 + o, vg + g);
    }
    CP_COMMIT();
    CP_WAIT0();
    __syncthreads();

    int mid = lane >> 3, r8 = lane & 7;
    uint32_t afr[4][4];
    #pragma unroll
    for (int s = 0; s < 4; s++) {
        int row = 16 * w + ((mid & 1) << 3) + r8;
        int cb = s * 2 + (mid >> 1);
        ldsm4(afr[s], sq + KVOFF(row, cb));
    }

    float o_acc[8][4];
    #pragma unroll
    for (int a = 0; a < 8; a++)
        #pragma unroll
        for (int i = 0; i < 4; i++) o_acc[a][i] = 0.f;
    float mr0 = -1e30f, mr1 = -1e30f, lr0 = 0.f, lr1 = 0.f;

    int nkt = qt + 1;
    int myrow0 = 16 * w + (lane >> 2);
    int mycol0 = 2 * (lane & 3);

    for (int kt = 0; kt < nkt; kt++) {
        __syncthreads();
        if (kt + 1 < nkt) {
            uint32_t dk = (kt & 1) ? sk0 : sk1;
            uint32_t dv = (kt & 1) ? sv0 : sv1;
            const char* kg_ = kg + (size_t)(kt + 1) * 64 * 128;
            const char* vg_ = vg + (size_t)(kt + 1) * 64 * 128;
            #pragma unroll
            for (int j = 0; j < 4; j++) {
                int i = tid + j * 128;
                int row = i >> 3, cb = i & 7;
                uint32_t o = KVOFF(row, cb);
                size_t g = (size_t)row * 128 + cb * 16;
                cp16(dk + o, kg_ + g);
                cp16(dv + o, vg_ + g);
            }
        }
        CP_COMMIT();
        CP_WAIT1();
        __syncthreads();

        uint32_t skb = (kt & 1) ? sk1 : sk0;
        uint32_t svb = (kt & 1) ? sv1 : sv0;

        float sA[8][4];
        #pragma unroll
        for (int e = 0; e < 8; e++)
            #pragma unroll
            for (int i = 0; i < 4; i++) sA[e][i] = 0.f;
        #pragma unroll
        for (int s = 0; s < 4; s++) {
            #pragma unroll
            for (int j = 0; j < 4; j++) {
                int row = j * 16 + ((mid >> 1) << 3) + r8;
                int cb = s * 2 + (mid & 1);
                uint32_t bk[4];
                ldsm4(bk, skb + KVOFF(row, cb));
                mma16816(sA[2*j],   afr[s], bk[0], bk[1]);
                mma16816(sA[2*j+1], afr[s], bk[2], bk[3]);
            }
        }

        #pragma unroll
        for (int e = 0; e < 8; e++)
            #pragma unroll
            for (int i = 0; i < 4; i++) sA[e][i] *= 0.03125f;
        if (kt == qt) {
            #pragma unroll
            for (int e = 0; e < 8; e++) {
                int kc = e * 8 + mycol0;
                if (kc     > myrow0)     sA[e][0] = -1e30f;
                if (kc + 1 > myrow0)     sA[e][1] = -1e30f;
                if (kc     > myrow0 + 8) sA[e][2] = -1e30f;
                if (kc + 1 > myrow0 + 8) sA[e][3] = -1e30f;
            }
        }

        float mx0 = -1e30f, mx1 = -1e30f;
        #pragma unroll
        for (int e = 0; e < 8; e++) {
            mx0 = fmaxf(mx0, fmaxf(sA[e][0], sA[e][1]));
            mx1 = fmaxf(mx1, fmaxf(sA[e][2], sA[e][3]));
        }
        mx0 = fmaxf(mx0, __shfl_xor_sync(0xffffffffu, mx0, 1));
        mx0 = fmaxf(mx0, __shfl_xor_sync(0xffffffffu, mx0, 2));
        mx1 = fmaxf(mx1, __shfl_xor_sync(0xffffffffu, mx1, 1));
        mx1 = fmaxf(mx1, __shfl_xor_sync(0xffffffffu, mx1, 2));
        float mn0 = fmaxf(mr0, mx0), mn1 = fmaxf(mr1, mx1);
        float al0 = __expf(mr0 - mn0), al1 = __expf(mr1 - mn1);
        mr0 = mn0; mr1 = mn1;

        float sum0 = 0.f, sum1 = 0.f;
        uint32_t pa[4][4];
        #pragma unroll
        for (int e = 0; e < 8; e++) {
            float p0 = __expf(sA[e][0] - mn0);
            float p1 = __expf(sA[e][1] - mn0);
            float p2 = __expf(sA[e][2] - mn1);
            float p3 = __expf(sA[e][3] - mn1);
            sum0 += p0 + p1; sum1 += p2 + p3;
            int t = e >> 1, od = (e & 1) * 2;
            pa[t][od]     = f22u(p0, p1);
            pa[t][od + 1] = f22u(p2, p3);
        }
        sum0 += __shfl_xor_sync(0xffffffffu, sum0, 1);
        sum0 += __shfl_xor_sync(0xffffffffu, sum0, 2);
        sum1 += __shfl_xor_sync(0xffffffffu, sum1, 1);
        sum1 += __shfl_xor_sync(0xffffffffu, sum1, 2);
        lr0 = lr0 * al0 + sum0;
        lr1 = lr1 * al1 + sum1;

        #pragma unroll
        for (int a = 0; a < 8; a++) {
            o_acc[a][0] *= al0; o_acc[a][1] *= al0;
            o_acc[a][2] *= al1; o_acc[a][3] *= al1;
        }

        #pragma unroll
        for (int t = 0; t < 4; t++) {
            #pragma unroll
            for (int j = 0; j < 4; j++) {
                int row = t * 16 + ((mid & 1) << 3) + r8;
                int cb = j * 2 + (mid >> 1);
                uint32_t bv[4];
                ldsm4t(bv, svb + KVOFF(row, cb));
                mma16816(o_acc[2*j],   pa[t], bv[0], bv[1]);
                mma16816(o_acc[2*j+1], pa[t], bv[2], bv[3]);
            }
        }
    }

    float inv0 = 1.0f / lr0, inv1 = 1.0f / lr1;
    int b = bh >> 4, h = bh & 15;
    int gr0 = q0 + myrow0, gr1 = gr0 + 8;
    #pragma unroll
    for (int a = 0; a < 8; a++) {
        int d = a * 8 + mycol0;
        *(uint32_t*)(Og + (((size_t)(b * T_ + gr0)) * H_ + h) * HS_ + d) =
            f22u(o_acc[a][0] * inv0, o_acc[a][1] * inv0);
        *(uint32_t*)(Og + (((size_t)(b * T_ + gr1)) * H_ + h) * HS_ + d) =
            f22u(o_acc[a][2] * inv1, o_acc[a][3] * inv1);
    }
}

// ---------------- launch --------------------------------------------------------
extern "C" void kernel_launch(void* const* d_in, const int* in_sizes, int n_in,
                              void* d_out, int out_size)
{
    const float* x    = (const float*)d_in[0];
    const float* Wq   = (const float*)d_in[1];
    const float* Wk   = (const float*)d_in[2];
    const float* Wv   = (const float*)d_in[3];
    const float* Wo   = (const float*)d_in[4];
    const float* bo   = (const float*)d_in[5];
    const float* W1   = (const float*)d_in[6];
    const float* b1   = (const float*)d_in[7];
    const float* W2   = (const float*)d_in[8];
    const float* b2   = (const float*)d_in[9];
    const float* ln1w = (const float*)d_in[10];
    const float* ln1b = (const float*)d_in[11];
    const float* ln2w = (const float*)d_in[12];
    const float* ln2b = (const float*)d_in[13];
    float* out = (float*)d_out;

    __half *ph, *pat, *pf1, *pq, *pk, *pv, *wqkv, *wo, *w1, *w2;
    cudaGetSymbolAddress((void**)&ph,   g_h);
    cudaGetSymbolAddress((void**)&pat,  g_at);
    cudaGetSymbolAddress((void**)&pf1,  g_f1);
    cudaGetSymbolAddress((void**)&pq,   g_q);
    cudaGetSymbolAddress((void**)&pk,   g_k);
    cudaGetSymbolAddress((void**)&pv,   g_v);
    cudaGetSymbolAddress((void**)&wqkv, g_wqkv);
    cudaGetSymbolAddress((void**)&wo,   g_wo);
    cudaGetSymbolAddress((void**)&w1,   g_w1);
    cudaGetSymbolAddress((void**)&w2,   g_w2);

    cudaFuncSetAttribute(tgemm_kernel<0>, cudaFuncAttributeMaxDynamicSharedMemorySize, SMEM_GEMM);
    cudaFuncSetAttribute(tgemm_kernel<1>, cudaFuncAttributeMaxDynamicSharedMemorySize, SMEM_GEMM);
    cudaFuncSetAttribute(tgemm_kernel<2>, cudaFuncAttributeMaxDynamicSharedMemorySize, SMEM_GEMM);

    dim3 tb(32, 8);

    // weight prep (transpose to fp16 [N,K])
    trans_qkv_kernel<<<dim3(2, 32, 48), tb>>>(Wq, Wk, Wv, wqkv);
    trans_kernel<<<dim3(32, 32), tb>>>(Wo, E_, E_, wo);
    trans_kernel<<<dim3(128, 32), tb>>>(W1, E_, FF_, w1);
    trans_kernel<<<dim3(32, 128), tb>>>(W2, FF_, E_, w2);

    // h = LN1(x) -> fp16
    ln_kernel<<<M_/8, 256>>>(x, ln1w, ln1b, ph);

    // q,k,v = h @ Wqkv (scatter fp16 [B,H,T,HS])
    tgemm_kernel<0><<<dim3(3*E_/256, M_/128), 256, SMEM_GEMM>>>(
        ph, wqkv, M_, 3*E_, E_,
        nullptr, nullptr, nullptr, nullptr, pq, pk, pv);

    // attention (HMMA flash) -> fp16 [B,T,H,HS]
    attn_kernel<<<dim3(T_/64, B_*H_), 128>>>(pq, pk, pv, pat);

    // x1 = x + attn @ Wo + bo  (fp32, into d_out)
    tgemm_kernel<1><<<dim3(E_/256, M_/128), 256, SMEM_GEMM>>>(
        pat, wo, M_, E_, E_,
        bo, x, out, nullptr, nullptr, nullptr, nullptr);

    // h2 = LN2(x1) -> fp16
    ln_kernel<<<M_/8, 256>>>(out, ln2w, ln2b, ph);

    // f1 = relu(h2 @ W1 + b1) -> fp16
    tgemm_kernel<2><<<dim3(FF_/256, M_/128), 256, SMEM_GEMM>>>(
        ph, w1, M_, FF_, E_,
        b1, nullptr, nullptr, pf1, nullptr, nullptr, nullptr);

    // out = x1 + f1 @ W2 + b2
    tgemm_kernel<1><<<dim3(E_/256, M_/128), 256, SMEM_GEMM>>>(
        pf1, w2, M_, E_, FF_,
        b2, out, out, nullptr, nullptr, nullptr, nullptr);
}